// round 13
// baseline (speedup 1.0000x reference)
#include <cuda_runtime.h>
#include <cuda_bf16.h>
#include <math.h>
#include <float.h>

// Problem constants (shapes are static per setup_inputs)
#define BB 8
#define DD 256
#define TT 2048
#define KNN 10
#define BETA 0.2f
#define THRESH 0.7f
#define MAXSPAN 4

// ---------------- device scratch (no allocs allowed) ----------------
__device__ float g_xn[(size_t)BB * TT * DD];          // 16 MiB  normalized [B,T,D]
__device__ float g_sim[(size_t)BB * TT * TT];         // 128 MiB sim [B,T,T]
__device__ float g_rho[BB * TT];
__device__ float g_rowmax[BB * TT];
__device__ float g_s[BB * TT];
__device__ int   g_lens[BB * TT];                     // ordered cluster lens (0 pad)
__device__ int   g_start[BB * TT];                    // ordered cluster start

// monotone float->uint mapping (order preserving for all floats)
__device__ __forceinline__ unsigned fmono(float v) {
    unsigned u = __float_as_uint(v);
    return (u & 0x80000000u) ? ~u : (u | 0x80000000u);
}
__device__ __forceinline__ float fmono_inv(unsigned m) {
    return __uint_as_float((m & 0x80000000u) ? (m & 0x7fffffffu) : ~m);
}

// packed f32x2 helpers (sm_100+): two independent IEEE-rn FMAs per instruction
__device__ __forceinline__ unsigned long long dup2(float a) {
    unsigned long long d;
    unsigned r = __float_as_uint(a);
    asm("mov.b64 %0, {%1, %1};" : "=l"(d) : "r"(r));
    return d;
}
__device__ __forceinline__ void ffma2(unsigned long long& d, unsigned long long a, unsigned long long b) {
    asm("fma.rn.f32x2 %0, %1, %2, %0;" : "+l"(d) : "l"(a), "l"(b));
}
__device__ __forceinline__ void unpack2(unsigned long long d, float& lo, float& hi) {
    unsigned rl, rh;
    asm("mov.b64 {%0, %1}, %2;" : "=r"(rl), "=r"(rh) : "l"(d));
    lo = __uint_as_float(rl);
    hi = __uint_as_float(rh);
}

// no-op kernel: shifts ncu's fixed capture slot (our 4th launch) onto k_topk
__global__ void k_nop() {}

// ---------------- K1: normalize + transpose ----------------
// x [B,D,T] -> g_xn [B,T,D], row-normalized over D
__global__ void k_normalize(const float* __restrict__ x) {
    __shared__ float tile[32 * 257];
    __shared__ float rinv[32];
    int b = blockIdx.y;
    int t0 = blockIdx.x * 32;
    const float* xb = x + (size_t)b * DD * TT;
    for (int i = threadIdx.x; i < 32 * 256; i += 256) {
        int tl = i & 31;
        int d  = i >> 5;
        tile[tl * 257 + d] = xb[(size_t)d * TT + t0 + tl];
    }
    __syncthreads();
    int w = threadIdx.x >> 5, lane = threadIdx.x & 31;
    for (int tk = w; tk < 32; tk += 8) {
        float ss = 0.f;
        #pragma unroll
        for (int j = 0; j < 8; j++) {
            float v = tile[tk * 257 + lane + 32 * j];
            ss += v * v;
        }
        #pragma unroll
        for (int o = 16; o > 0; o >>= 1) ss += __shfl_xor_sync(0xffffffffu, ss, o);
        if (lane == 0) rinv[tk] = 1.0f / fmaxf(sqrtf(ss), 1e-12f);
    }
    __syncthreads();
    float* xnb = g_xn + (size_t)b * TT * DD;
    for (int i = threadIdx.x; i < 32 * 256; i += 256) {
        int tk = i >> 8;
        int d  = i & 255;
        xnb[(size_t)(t0 + tk) * DD + d] = tile[tk * 257 + d] * rinv[tk];
    }
}

// ---------------- K2: symmetric GEMM sim = (Xn Xn^T + 1)/2 ----------------
// 128x128 tile per block, BK=8, 256 threads, 8x8 per thread.
// Double-buffered smem, one barrier per k-iter; packed fma.rn.f32x2 inner loop.
// A-fragments fetched via 1 LDS.32 + warp shuffles (64B unique per warp per k
// instead of 512B through the LSU) — cuts l1tex wavefronts ~16->9 per warp/k.
// Only upper-triangular tile pairs computed; mirror written for off-diagonal.
__global__ void __launch_bounds__(256, 2) k_gemm_sim() {
    int b = blockIdx.y;
    int p = blockIdx.x;
    int bi = 0, cnt = 16;
    while (p >= cnt) { p -= cnt; bi++; cnt--; }
    int bj = bi + p;

    const float* A = g_xn + (size_t)b * TT * DD;
    float* C = g_sim + (size_t)b * TT * TT;

    __shared__ float As[2][8][132];
    __shared__ float Bs[2][8][132];

    int tid = threadIdx.x;
    int lane = tid & 31;
    int tx = tid & 15, ty = tid >> 4;
    int i0 = ty * 8, j0 = tx * 8;
    int halfbase = lane & 16;       // lane id of slot 0 of my half-warp
    int asub = i0 + (lane & 7);     // my A-slot within the tile row

    // acc2[ii][jp] = packed pair (acc[ii][2*jp], acc[ii][2*jp+1])
    unsigned long long acc2[8][4];
    #pragma unroll
    for (int i = 0; i < 8; i++)
        #pragma unroll
        for (int j = 0; j < 4; j++) acc2[i][j] = 0ull;

    int lr = tid >> 1;
    int lk = (tid & 1) * 4;
    const float* Arow = A + (size_t)(bi * 128 + lr) * DD + lk;
    const float* Brow = A + (size_t)(bj * 128 + lr) * DD + lk;

    // prologue: load tile 0 and stage into buffer 0
    {
        float4 av = *(const float4*)(Arow);
        float4 bv = *(const float4*)(Brow);
        As[0][lk + 0][lr] = av.x; As[0][lk + 1][lr] = av.y;
        As[0][lk + 2][lr] = av.z; As[0][lk + 3][lr] = av.w;
        Bs[0][lk + 0][lr] = bv.x; Bs[0][lk + 1][lr] = bv.y;
        Bs[0][lk + 2][lr] = bv.z; Bs[0][lk + 3][lr] = bv.w;
    }
    __syncthreads();

    int cur = 0;
    for (int kt = 0; kt < DD; kt += 8) {
        float4 av, bv;
        bool more = (kt + 8 < DD);
        if (more) {
            av = *(const float4*)(Arow + kt + 8);
            bv = *(const float4*)(Brow + kt + 8);
        }
        #pragma unroll
        for (int k = 0; k < 8; k++) {
            // one scalar LDS per lane covers both halves' A fragments
            float aval = As[cur][k][asub];
            float avals[8];
            #pragma unroll
            for (int ii = 0; ii < 8; ii++)
                avals[ii] = __shfl_sync(0xffffffffu, aval, halfbase + ii);
            // B pairs read as packed u64 lanes (lo = even col)
            ulonglong2 bq0 = *(const ulonglong2*)&Bs[cur][k][j0];
            ulonglong2 bq1 = *(const ulonglong2*)&Bs[cur][k][j0 + 4];
            #pragma unroll
            for (int ii = 0; ii < 8; ii++) {
                unsigned long long ad = dup2(avals[ii]);
                ffma2(acc2[ii][0], ad, bq0.x);
                ffma2(acc2[ii][1], ad, bq0.y);
                ffma2(acc2[ii][2], ad, bq1.x);
                ffma2(acc2[ii][3], ad, bq1.y);
            }
        }
        if (more) {
            int nxt = cur ^ 1;
            As[nxt][lk + 0][lr] = av.x; As[nxt][lk + 1][lr] = av.y;
            As[nxt][lk + 2][lr] = av.z; As[nxt][lk + 3][lr] = av.w;
            Bs[nxt][lk + 0][lr] = bv.x; Bs[nxt][lk + 1][lr] = bv.y;
            Bs[nxt][lk + 2][lr] = bv.z; Bs[nxt][lk + 3][lr] = bv.w;
            __syncthreads();
            cur = nxt;
        }
    }

    // unpack accumulators
    float acc[8][8];
    #pragma unroll
    for (int ii = 0; ii < 8; ii++)
        #pragma unroll
        for (int jp = 0; jp < 4; jp++)
            unpack2(acc2[ii][jp], acc[ii][2 * jp], acc[ii][2 * jp + 1]);

    int gi = bi * 128 + i0;
    int gj = bj * 128 + j0;
    #pragma unroll
    for (int ii = 0; ii < 8; ii++) {
        float4 v0, v1;
        v0.x = (acc[ii][0] + 1.f) * 0.5f; v0.y = (acc[ii][1] + 1.f) * 0.5f;
        v0.z = (acc[ii][2] + 1.f) * 0.5f; v0.w = (acc[ii][3] + 1.f) * 0.5f;
        v1.x = (acc[ii][4] + 1.f) * 0.5f; v1.y = (acc[ii][5] + 1.f) * 0.5f;
        v1.z = (acc[ii][6] + 1.f) * 0.5f; v1.w = (acc[ii][7] + 1.f) * 0.5f;
        *(float4*)&C[(size_t)(gi + ii) * TT + gj]     = v0;
        *(float4*)&C[(size_t)(gi + ii) * TT + gj + 4] = v1;
    }
    if (bi != bj) {
        #pragma unroll
        for (int jj = 0; jj < 8; jj++) {
            float4 v0, v1;
            v0.x = (acc[0][jj] + 1.f) * 0.5f; v0.y = (acc[1][jj] + 1.f) * 0.5f;
            v0.z = (acc[2][jj] + 1.f) * 0.5f; v0.w = (acc[3][jj] + 1.f) * 0.5f;
            v1.x = (acc[4][jj] + 1.f) * 0.5f; v1.y = (acc[5][jj] + 1.f) * 0.5f;
            v1.z = (acc[6][jj] + 1.f) * 0.5f; v1.w = (acc[7][jj] + 1.f) * 0.5f;
            *(float4*)&C[(size_t)(gj + jj) * TT + gi]     = v0;
            *(float4*)&C[(size_t)(gj + jj) * TT + gi + 4] = v1;
        }
    }
}

// ---------------- K3: per-row top-11 -> rho, rowmax (register-resident) ----------------
__global__ void __launch_bounds__(256) k_topk() {
    __shared__ float cand[8 * (KNN + 1)];
    int gid = blockIdx.x; // b*T + i
    const float* srow = g_sim + (size_t)gid * TT;
    int tid = threadIdx.x;
    int w = tid >> 5, lane = tid & 31;

    float v[8];
    const float4* pp = (const float4*)(srow + w * 256 + lane * 8);
    float4 aa = pp[0], bb = pp[1];
    v[0] = aa.x; v[1] = aa.y; v[2] = aa.z; v[3] = aa.w;
    v[4] = bb.x; v[5] = bb.y; v[6] = bb.z; v[7] = bb.w;

    #pragma unroll
    for (int r = 0; r < KNN + 1; r++) {
        float m = v[0]; int mi = 0;
        #pragma unroll
        for (int q = 1; q < 8; q++) if (v[q] > m) { m = v[q]; mi = q; }
        unsigned long long pk = ((unsigned long long)fmono(m) << 32) | (unsigned)((lane << 3) | mi);
        #pragma unroll
        for (int o = 16; o > 0; o >>= 1) {
            unsigned long long o2 = __shfl_xor_sync(0xffffffffu, pk, o);
            pk = pk > o2 ? pk : o2;
        }
        int widx = (int)(pk & 0xffu);
        if ((widx >> 3) == lane) v[widx & 7] = -2.0f;   // winner clears its slot
        if (lane == 0) cand[w * (KNN + 1) + r] = fmono_inv((unsigned)(pk >> 32));
    }
    __syncthreads();

    if (w == 0) {
        float c0 = cand[lane];
        float c1 = cand[lane + 32];
        float c2 = (lane + 64 < 88) ? cand[lane + 64] : -2.0f;
        float maxv = 0.f, sum = 0.f;
        #pragma unroll
        for (int r = 0; r < KNN + 1; r++) {
            float m = c0; int mi = 0;
            if (c1 > m) { m = c1; mi = 1; }
            if (c2 > m) { m = c2; mi = 2; }
            unsigned long long pk = ((unsigned long long)fmono(m) << 32) | (unsigned)((lane << 2) | mi);
            #pragma unroll
            for (int o = 16; o > 0; o >>= 1) {
                unsigned long long o2 = __shfl_xor_sync(0xffffffffu, pk, o);
                pk = pk > o2 ? pk : o2;
            }
            int widx = (int)(pk & 0xffu);
            if ((widx >> 2) == lane) {
                int s = widx & 3;
                if (s == 0) c0 = -2.0f; else if (s == 1) c1 = -2.0f; else c2 = -2.0f;
            }
            float win = fmono_inv((unsigned)(pk >> 32));
            if (r == 0) maxv = win; else sum += win;
        }
        if (lane == 0) {
            g_rowmax[gid] = maxv;
            g_rho[gid] = expf(-sum * (1.0f / KNN));
        }
    }
}

// ---------------- K4: delta, s = rho*delta (branchless float4) ----------------
__global__ void __launch_bounds__(256) k_delta() {
    __shared__ float smin[8];
    int gid = blockIdx.x;
    int b = gid >> 11;
    const float4* __restrict__ srow4 = (const float4*)(g_sim + (size_t)gid * TT);
    const float4* __restrict__ rho4  = (const float4*)(g_rho + (size_t)b * TT);
    float ri = g_rho[gid];
    int tid = threadIdx.x;
    float mn0 = FLT_MAX, mn1 = FLT_MAX;
    #pragma unroll
    for (int it = 0; it < 2; it++) {
        int i = tid + it * 256;
        float4 r4 = rho4[i];
        float4 s4 = srow4[i];
        mn0 = fminf(mn0, r4.x > ri ? s4.x : FLT_MAX);
        mn1 = fminf(mn1, r4.y > ri ? s4.y : FLT_MAX);
        mn0 = fminf(mn0, r4.z > ri ? s4.z : FLT_MAX);
        mn1 = fminf(mn1, r4.w > ri ? s4.w : FLT_MAX);
    }
    float mn = fminf(mn0, mn1);
    #pragma unroll
    for (int o = 16; o > 0; o >>= 1)
        mn = fminf(mn, __shfl_xor_sync(0xffffffffu, mn, o));
    if ((tid & 31) == 0) smin[tid >> 5] = mn;
    __syncthreads();
    if (tid == 0) {
        float m = smin[0];
        #pragma unroll
        for (int w = 1; w < 8; w++) m = fminf(m, smin[w]);
        float delta = (m < FLT_MAX) ? m : g_rowmax[gid];
        g_s[gid] = ri * delta;
    }
}

// ---------------- K5: sort + sequential clustering (1 block / batch) ----------------
// Threshold tests precomputed as an 8-bit mask per token (bit j: neighbor
// offset j-4 for j<4, j-3 for j>=4). Same fp expression as reference ->
// bit-identical decisions. Serial walk then needs 1 mask LDS per seed.
#define SV_OFF    0                      // float[2048]  : 8192
#define KEYS_OFF  8192                   // u64[2048]    : 16384
#define MASK_OFF  24576                  // uchar[2048]  : 2048
#define ASG_OFF   26624                  // uchar[2048]  : 2048
#define LENS_OFF  28672                  // int[2048]    : 8192
#define START_OFF 36864                  // int[2048]    : 8192
#define FLAG_OFF  45056                  // int[2048]    : 8192
#define PART_OFF  53248                  // int[256]     : 1024
#define MISC_OFF  54272                  // int[4]
#define SMEM5     54288

__global__ void k_cluster() {
    extern __shared__ unsigned char smemraw[];
    float* sv  = (float*)(smemraw + SV_OFF);
    unsigned long long* keys = (unsigned long long*)(smemraw + KEYS_OFF);
    unsigned char* maskArr = smemraw + MASK_OFF;
    unsigned char* assigned = smemraw + ASG_OFF;
    int* lensc  = (int*)(smemraw + LENS_OFF);
    int* startc = (int*)(smemraw + START_OFF);
    int* flag   = (int*)(smemraw + FLAG_OFF);
    int* part   = (int*)(smemraw + PART_OFF);
    int* misc   = (int*)(smemraw + MISC_OFF);

    int b = blockIdx.x;
    int tid = threadIdx.x;

    for (int t = tid; t < TT; t += 256) {
        float s = g_s[b * TT + t];
        sv[t] = s;
        keys[t] = ((unsigned long long)(~fmono(s)) << 32) | (unsigned)t;
        assigned[t] = 0;
    }
    __syncthreads();   // sv complete before mask computation reads it

    // mask[t] bit j: sim[t, t+off] - BETA*s[t+off] > THRESH  (off = j-4 / j-3)
    for (int t = tid; t < TT; t += 256) {
        const float* srow = g_sim + ((size_t)b * TT + t) * TT;
        unsigned m = 0;
        #pragma unroll
        for (int j = 0; j < 8; j++) {
            int off = (j < 4) ? (j - 4) : (j - 3);
            int tt = t + off;
            if (tt >= 0 && tt < TT) {
                float v = srow[tt];
                if (v - BETA * sv[tt] > THRESH) m |= (1u << j);
            }
        }
        maskArr[t] = (unsigned char)m;
    }
    __syncthreads();

    // bitonic sort (ascending u64): primary ~fmono(s) => s descending; tie: low index first
    for (int size = 2; size <= TT; size <<= 1) {
        for (int stride = size >> 1; stride > 0; stride >>= 1) {
            __syncthreads();
            for (int i = tid; i < TT; i += 256) {
                int ixj = i ^ stride;
                if (ixj > i) {
                    bool asc = ((i & size) == 0);
                    unsigned long long a = keys[i], c = keys[ixj];
                    if ((a > c) == asc) { keys[i] = c; keys[ixj] = a; }
                }
            }
        }
    }
    __syncthreads();

    if (tid == 0) {
        int ncl = 0;
        for (int k = 0; k < TT; k++) {
            int seed = (int)(keys[k] & 0xffffffffu);
            if (assigned[seed]) continue;
            assigned[seed] = 1;
            unsigned m = maskArr[seed];
            int size = 1, start = seed;
            bool alive = true;
            #pragma unroll
            for (int off = 1; off <= MAXSPAN; off++) {
                int t = seed + off;
                bool ok = alive && (t < TT) && (!assigned[t]) && (size < MAXSPAN) &&
                          ((m >> (3 + off)) & 1u);
                if (ok) { assigned[t] = 1; size++; }
                alive = ok;
            }
            alive = true;
            #pragma unroll
            for (int off = 1; off <= MAXSPAN; off++) {
                int t = seed - off;
                bool ok = alive && (t >= 0) && (!assigned[t]) && (size < MAXSPAN) &&
                          ((m >> (4 - off)) & 1u);
                if (ok) { assigned[t] = 1; start = t; size++; }
                alive = ok;
            }
            lensc[ncl] = size;
            startc[ncl] = start;
            ncl++;
        }
        misc[0] = ncl;
    }
    __syncthreads();
    int ncl = misc[0];

    // rank clusters by start (intervals tile [0,T), starts distinct)
    for (int i = tid; i < TT; i += 256) flag[i] = 0;
    __syncthreads();
    for (int c = tid; c < ncl; c += 256) flag[startc[c]] = 1;
    __syncthreads();
    int base = tid * 8;
    int tmp[8];
    {
        int run = 0;
        #pragma unroll
        for (int q = 0; q < 8; q++) { tmp[q] = run; run += flag[base + q]; }
        part[tid] = run;
    }
    __syncthreads();
    if (tid == 0) {
        int r = 0;
        for (int i = 0; i < 256; i++) { int v = part[i]; part[i] = r; r += v; }
    }
    __syncthreads();
    {
        int off = part[tid];
        #pragma unroll
        for (int q = 0; q < 8; q++) flag[base + q] = off + tmp[q];
    }
    __syncthreads();

    for (int i = tid; i < TT; i += 256) { g_lens[b * TT + i] = 0; g_start[b * TT + i] = 0; }
    __syncthreads();
    for (int c = tid; c < ncl; c += 256) {
        int r = flag[startc[c]];
        g_lens[b * TT + r] = lensc[c];
        g_start[b * TT + r] = startc[c];
    }
}

// ---------------- K6: output (cluster means + lens) ----------------
__global__ void k_output(const float* __restrict__ x, float* __restrict__ out, int out_size) {
    int idx = blockIdx.x * 256 + threadIdx.x;
    if (idx >= out_size) return;
    const int EMB = BB * DD * TT;
    if (out_size == BB * TT) { // lens-only output variant
        out[idx] = (float)g_lens[idx];
        return;
    }
    if (idx < EMB) {
        int b = idx >> 19;         // D*T = 2^19
        int rem = idx & (DD * TT - 1);
        int d = rem >> 11;
        int r = rem & (TT - 1);
        int len = g_lens[b * TT + r];
        float v = 0.f;
        if (len > 0) {
            int st = g_start[b * TT + r];
            const float* xp = x + ((size_t)b << 19) + ((size_t)d << 11) + st;
            float sum = 0.f;
            #pragma unroll 4
            for (int k = 0; k < len; k++) sum += xp[k];
            v = sum / (float)len;
        }
        out[idx] = v;
    } else {
        int li = idx - EMB;
        out[idx] = (float)g_lens[li];
    }
}

// ---------------- launcher ----------------
extern "C" void kernel_launch(void* const* d_in, const int* in_sizes, int n_in,
                              void* d_out, int out_size) {
    const float* x = (const float*)d_in[0];
    float* out = (float*)d_out;

    k_normalize<<<dim3(TT / 32, BB), 256>>>(x);
    // one no-op so k_topk is the 4th launch -> lands in ncu's capture slot
    k_nop<<<1, 1>>>();
    k_gemm_sim<<<dim3(136, BB), 256>>>();
    k_topk<<<BB * TT, 256>>>();
    k_delta<<<BB * TT, 256>>>();

    cudaFuncSetAttribute(k_cluster, cudaFuncAttributeMaxDynamicSharedMemorySize, SMEM5);
    k_cluster<<<BB, 256, SMEM5>>>();

    k_output<<<(out_size + 255) / 256, 256>>>(x, out, out_size);
}

// round 14
// speedup vs baseline: 1.2160x; 1.2160x over previous
#include <cuda_runtime.h>
#include <cuda_bf16.h>
#include <math.h>
#include <float.h>

// Problem constants (shapes are static per setup_inputs)
#define BB 8
#define DD 256
#define TT 2048
#define KNN 10
#define BETA 0.2f
#define THRESH 0.7f
#define MAXSPAN 4

// ---------------- device scratch (no allocs allowed) ----------------
__device__ float g_xn[(size_t)BB * TT * DD];          // 16 MiB  normalized [B,T,D]
__device__ float g_sim[(size_t)BB * TT * TT];         // 128 MiB sim [B,T,T]
__device__ float g_rho[BB * TT];
__device__ float g_rowmax[BB * TT];
__device__ float g_s[BB * TT];
__device__ int   g_lens[BB * TT];                     // ordered cluster lens (0 pad)
__device__ int   g_start[BB * TT];                    // ordered cluster start

// monotone float->uint mapping (order preserving for all floats)
__device__ __forceinline__ unsigned fmono(float v) {
    unsigned u = __float_as_uint(v);
    return (u & 0x80000000u) ? ~u : (u | 0x80000000u);
}
__device__ __forceinline__ float fmono_inv(unsigned m) {
    return __uint_as_float((m & 0x80000000u) ? (m & 0x7fffffffu) : ~m);
}

// packed f32x2 helpers (sm_100+): two independent IEEE-rn FMAs per instruction
__device__ __forceinline__ unsigned long long dup2(float a) {
    unsigned long long d;
    unsigned r = __float_as_uint(a);
    asm("mov.b64 %0, {%1, %1};" : "=l"(d) : "r"(r));
    return d;
}
__device__ __forceinline__ void ffma2(unsigned long long& d, unsigned long long a, unsigned long long b) {
    asm("fma.rn.f32x2 %0, %1, %2, %0;" : "+l"(d) : "l"(a), "l"(b));
}
__device__ __forceinline__ void unpack2(unsigned long long d, float& lo, float& hi) {
    unsigned rl, rh;
    asm("mov.b64 {%0, %1}, %2;" : "=r"(rl), "=r"(rh) : "l"(d));
    lo = __uint_as_float(rl);
    hi = __uint_as_float(rh);
}

// no-op kernel: shifts ncu's fixed capture slot (our 4th launch)
__global__ void k_nop() {}

// ---------------- K1: normalize + transpose ----------------
// x [B,D,T] -> g_xn [B,T,D], row-normalized over D
__global__ void k_normalize(const float* __restrict__ x) {
    __shared__ float tile[32 * 257];
    __shared__ float rinv[32];
    int b = blockIdx.y;
    int t0 = blockIdx.x * 32;
    const float* xb = x + (size_t)b * DD * TT;
    for (int i = threadIdx.x; i < 32 * 256; i += 256) {
        int tl = i & 31;
        int d  = i >> 5;
        tile[tl * 257 + d] = xb[(size_t)d * TT + t0 + tl];
    }
    __syncthreads();
    int w = threadIdx.x >> 5, lane = threadIdx.x & 31;
    for (int tk = w; tk < 32; tk += 8) {
        float ss = 0.f;
        #pragma unroll
        for (int j = 0; j < 8; j++) {
            float v = tile[tk * 257 + lane + 32 * j];
            ss += v * v;
        }
        #pragma unroll
        for (int o = 16; o > 0; o >>= 1) ss += __shfl_xor_sync(0xffffffffu, ss, o);
        if (lane == 0) rinv[tk] = 1.0f / fmaxf(sqrtf(ss), 1e-12f);
    }
    __syncthreads();
    float* xnb = g_xn + (size_t)b * TT * DD;
    for (int i = threadIdx.x; i < 32 * 256; i += 256) {
        int tk = i >> 8;
        int d  = i & 255;
        xnb[(size_t)(t0 + tk) * DD + d] = tile[tk * 257 + d] * rinv[tk];
    }
}

// ---------------- K2: symmetric GEMM sim = (Xn Xn^T + 1)/2 ----------------
// (Round-12 measured config: 244us.) 128x128 tile, BK=8, 256 threads, 8x8/thread,
// double-buffered smem, packed fma.rn.f32x2 inner loop.
__global__ void __launch_bounds__(256) k_gemm_sim() {
    int b = blockIdx.y;
    int p = blockIdx.x;
    int bi = 0, cnt = 16;
    while (p >= cnt) { p -= cnt; bi++; cnt--; }
    int bj = bi + p;

    const float* A = g_xn + (size_t)b * TT * DD;
    float* C = g_sim + (size_t)b * TT * TT;

    __shared__ float As[2][8][132];
    __shared__ float Bs[2][8][132];

    int tid = threadIdx.x;
    int tx = tid & 15, ty = tid >> 4;
    int i0 = ty * 8, j0 = tx * 8;

    unsigned long long acc2[8][4];
    #pragma unroll
    for (int i = 0; i < 8; i++)
        #pragma unroll
        for (int j = 0; j < 4; j++) acc2[i][j] = 0ull;

    int lr = tid >> 1;
    int lk = (tid & 1) * 4;
    const float* Arow = A + (size_t)(bi * 128 + lr) * DD + lk;
    const float* Brow = A + (size_t)(bj * 128 + lr) * DD + lk;

    {
        float4 av = *(const float4*)(Arow);
        float4 bv = *(const float4*)(Brow);
        As[0][lk + 0][lr] = av.x; As[0][lk + 1][lr] = av.y;
        As[0][lk + 2][lr] = av.z; As[0][lk + 3][lr] = av.w;
        Bs[0][lk + 0][lr] = bv.x; Bs[0][lk + 1][lr] = bv.y;
        Bs[0][lk + 2][lr] = bv.z; Bs[0][lk + 3][lr] = bv.w;
    }
    __syncthreads();

    int cur = 0;
    for (int kt = 0; kt < DD; kt += 8) {
        float4 av, bv;
        bool more = (kt + 8 < DD);
        if (more) {
            av = *(const float4*)(Arow + kt + 8);
            bv = *(const float4*)(Brow + kt + 8);
        }
        #pragma unroll
        for (int k = 0; k < 8; k++) {
            float4 a0 = *(const float4*)&As[cur][k][i0];
            float4 a1 = *(const float4*)&As[cur][k][i0 + 4];
            ulonglong2 bq0 = *(const ulonglong2*)&Bs[cur][k][j0];
            ulonglong2 bq1 = *(const ulonglong2*)&Bs[cur][k][j0 + 4];
            float ar[8] = {a0.x, a0.y, a0.z, a0.w, a1.x, a1.y, a1.z, a1.w};
            #pragma unroll
            for (int ii = 0; ii < 8; ii++) {
                unsigned long long ad = dup2(ar[ii]);
                ffma2(acc2[ii][0], ad, bq0.x);
                ffma2(acc2[ii][1], ad, bq0.y);
                ffma2(acc2[ii][2], ad, bq1.x);
                ffma2(acc2[ii][3], ad, bq1.y);
            }
        }
        if (more) {
            int nxt = cur ^ 1;
            As[nxt][lk + 0][lr] = av.x; As[nxt][lk + 1][lr] = av.y;
            As[nxt][lk + 2][lr] = av.z; As[nxt][lk + 3][lr] = av.w;
            Bs[nxt][lk + 0][lr] = bv.x; Bs[nxt][lk + 1][lr] = bv.y;
            Bs[nxt][lk + 2][lr] = bv.z; Bs[nxt][lk + 3][lr] = bv.w;
            __syncthreads();
            cur = nxt;
        }
    }

    float acc[8][8];
    #pragma unroll
    for (int ii = 0; ii < 8; ii++)
        #pragma unroll
        for (int jp = 0; jp < 4; jp++)
            unpack2(acc2[ii][jp], acc[ii][2 * jp], acc[ii][2 * jp + 1]);

    int gi = bi * 128 + i0;
    int gj = bj * 128 + j0;
    #pragma unroll
    for (int ii = 0; ii < 8; ii++) {
        float4 v0, v1;
        v0.x = (acc[ii][0] + 1.f) * 0.5f; v0.y = (acc[ii][1] + 1.f) * 0.5f;
        v0.z = (acc[ii][2] + 1.f) * 0.5f; v0.w = (acc[ii][3] + 1.f) * 0.5f;
        v1.x = (acc[ii][4] + 1.f) * 0.5f; v1.y = (acc[ii][5] + 1.f) * 0.5f;
        v1.z = (acc[ii][6] + 1.f) * 0.5f; v1.w = (acc[ii][7] + 1.f) * 0.5f;
        *(float4*)&C[(size_t)(gi + ii) * TT + gj]     = v0;
        *(float4*)&C[(size_t)(gi + ii) * TT + gj + 4] = v1;
    }
    if (bi != bj) {
        #pragma unroll
        for (int jj = 0; jj < 8; jj++) {
            float4 v0, v1;
            v0.x = (acc[0][jj] + 1.f) * 0.5f; v0.y = (acc[1][jj] + 1.f) * 0.5f;
            v0.z = (acc[2][jj] + 1.f) * 0.5f; v0.w = (acc[3][jj] + 1.f) * 0.5f;
            v1.x = (acc[4][jj] + 1.f) * 0.5f; v1.y = (acc[5][jj] + 1.f) * 0.5f;
            v1.z = (acc[6][jj] + 1.f) * 0.5f; v1.w = (acc[7][jj] + 1.f) * 0.5f;
            *(float4*)&C[(size_t)(gj + jj) * TT + gi]     = v0;
            *(float4*)&C[(size_t)(gj + jj) * TT + gi + 4] = v1;
        }
    }
}

// ---------------- K3: per-row top-11 -> rho, rowmax (register-resident) ----------------
__global__ void __launch_bounds__(256) k_topk() {
    __shared__ float cand[8 * (KNN + 1)];
    int gid = blockIdx.x; // b*T + i
    const float* srow = g_sim + (size_t)gid * TT;
    int tid = threadIdx.x;
    int w = tid >> 5, lane = tid & 31;

    float v[8];
    const float4* pp = (const float4*)(srow + w * 256 + lane * 8);
    float4 aa = pp[0], bb = pp[1];
    v[0] = aa.x; v[1] = aa.y; v[2] = aa.z; v[3] = aa.w;
    v[4] = bb.x; v[5] = bb.y; v[6] = bb.z; v[7] = bb.w;

    #pragma unroll
    for (int r = 0; r < KNN + 1; r++) {
        float m = v[0]; int mi = 0;
        #pragma unroll
        for (int q = 1; q < 8; q++) if (v[q] > m) { m = v[q]; mi = q; }
        unsigned long long pk = ((unsigned long long)fmono(m) << 32) | (unsigned)((lane << 3) | mi);
        #pragma unroll
        for (int o = 16; o > 0; o >>= 1) {
            unsigned long long o2 = __shfl_xor_sync(0xffffffffu, pk, o);
            pk = pk > o2 ? pk : o2;
        }
        int widx = (int)(pk & 0xffu);
        if ((widx >> 3) == lane) v[widx & 7] = -2.0f;   // winner clears its slot
        if (lane == 0) cand[w * (KNN + 1) + r] = fmono_inv((unsigned)(pk >> 32));
    }
    __syncthreads();

    if (w == 0) {
        float c0 = cand[lane];
        float c1 = cand[lane + 32];
        float c2 = (lane + 64 < 88) ? cand[lane + 64] : -2.0f;
        float maxv = 0.f, sum = 0.f;
        #pragma unroll
        for (int r = 0; r < KNN + 1; r++) {
            float m = c0; int mi = 0;
            if (c1 > m) { m = c1; mi = 1; }
            if (c2 > m) { m = c2; mi = 2; }
            unsigned long long pk = ((unsigned long long)fmono(m) << 32) | (unsigned)((lane << 2) | mi);
            #pragma unroll
            for (int o = 16; o > 0; o >>= 1) {
                unsigned long long o2 = __shfl_xor_sync(0xffffffffu, pk, o);
                pk = pk > o2 ? pk : o2;
            }
            int widx = (int)(pk & 0xffu);
            if ((widx >> 2) == lane) {
                int s = widx & 3;
                if (s == 0) c0 = -2.0f; else if (s == 1) c1 = -2.0f; else c2 = -2.0f;
            }
            float win = fmono_inv((unsigned)(pk >> 32));
            if (r == 0) maxv = win; else sum += win;
        }
        if (lane == 0) {
            g_rowmax[gid] = maxv;
            g_rho[gid] = expf(-sum * (1.0f / KNN));
        }
    }
}

// ---------------- K4: delta, s = rho*delta (branchless float4) ----------------
__global__ void __launch_bounds__(256) k_delta() {
    __shared__ float smin[8];
    int gid = blockIdx.x;
    int b = gid >> 11;
    const float4* __restrict__ srow4 = (const float4*)(g_sim + (size_t)gid * TT);
    const float4* __restrict__ rho4  = (const float4*)(g_rho + (size_t)b * TT);
    float ri = g_rho[gid];
    int tid = threadIdx.x;
    float mn0 = FLT_MAX, mn1 = FLT_MAX;
    #pragma unroll
    for (int it = 0; it < 2; it++) {
        int i = tid + it * 256;
        float4 r4 = rho4[i];
        float4 s4 = srow4[i];
        mn0 = fminf(mn0, r4.x > ri ? s4.x : FLT_MAX);
        mn1 = fminf(mn1, r4.y > ri ? s4.y : FLT_MAX);
        mn0 = fminf(mn0, r4.z > ri ? s4.z : FLT_MAX);
        mn1 = fminf(mn1, r4.w > ri ? s4.w : FLT_MAX);
    }
    float mn = fminf(mn0, mn1);
    #pragma unroll
    for (int o = 16; o > 0; o >>= 1)
        mn = fminf(mn, __shfl_xor_sync(0xffffffffu, mn, o));
    if ((tid & 31) == 0) smin[tid >> 5] = mn;
    __syncthreads();
    if (tid == 0) {
        float m = smin[0];
        #pragma unroll
        for (int w = 1; w < 8; w++) m = fminf(m, smin[w]);
        float delta = (m < FLT_MAX) ? m : g_rowmax[gid];
        g_s[gid] = ri * delta;
    }
}

// ---------------- K5: sort + sequential clustering (1 block / batch) ----------------
// key u64 = (~fmono(s))<<32 | t<<8 | mask  (sort: s desc, t asc; mask free rider)
// assigned = 64-word bitset; serial walk does ~2 parallel LDS + register bit-ops
// per iteration instead of up to 10 dependent byte LDS/STS.
#define SV_OFF    0                      // float[2048]  : 8192
#define KEYS_OFF  8192                   // u64[2048]    : 16384
#define ABITS_OFF 24576                  // u32[64]      : 256
#define LENS_OFF  24832                  // int[2048]    : 8192
#define START_OFF 33024                  // int[2048]    : 8192
#define FLAG_OFF  41216                  // int[2048]    : 8192
#define PART_OFF  49408                  // int[256]     : 1024
#define MISC_OFF  50432                  // int[4]
#define SMEM5     50448

__global__ void k_cluster() {
    extern __shared__ unsigned char smemraw[];
    float* sv  = (float*)(smemraw + SV_OFF);
    unsigned long long* keys = (unsigned long long*)(smemraw + KEYS_OFF);
    unsigned* abits = (unsigned*)(smemraw + ABITS_OFF);
    int* lensc  = (int*)(smemraw + LENS_OFF);
    int* startc = (int*)(smemraw + START_OFF);
    int* flag   = (int*)(smemraw + FLAG_OFF);
    int* part   = (int*)(smemraw + PART_OFF);
    int* misc   = (int*)(smemraw + MISC_OFF);

    int b = blockIdx.x;
    int tid = threadIdx.x;

    for (int t = tid; t < TT; t += 256) sv[t] = g_s[b * TT + t];
    if (tid < 64) abits[tid] = 0u;
    __syncthreads();   // sv complete before mask computation reads it

    // key: high = ~fmono(s) (s desc), low = t<<8 | mask
    // mask bit j: sim[t, t+off] - BETA*s[t+off] > THRESH (off = j-4 for j<4, j-3 else)
    for (int t = tid; t < TT; t += 256) {
        const float* srow = g_sim + ((size_t)b * TT + t) * TT;
        unsigned m = 0;
        #pragma unroll
        for (int j = 0; j < 8; j++) {
            int off = (j < 4) ? (j - 4) : (j - 3);
            int tt = t + off;
            if (tt >= 0 && tt < TT) {
                float v = srow[tt];
                if (v - BETA * sv[tt] > THRESH) m |= (1u << j);
            }
        }
        keys[t] = ((unsigned long long)(~fmono(sv[t])) << 32) | (unsigned)((t << 8) | m);
    }
    __syncthreads();

    // bitonic sort (ascending u64)
    for (int size = 2; size <= TT; size <<= 1) {
        for (int stride = size >> 1; stride > 0; stride >>= 1) {
            __syncthreads();
            for (int i = tid; i < TT; i += 256) {
                int ixj = i ^ stride;
                if (ixj > i) {
                    bool asc = ((i & size) == 0);
                    unsigned long long a = keys[i], c = keys[ixj];
                    if ((a > c) == asc) { keys[i] = c; keys[ixj] = a; }
                }
            }
        }
    }
    __syncthreads();

    if (tid == 0) {
        int ncl = 0;
        for (int k = 0; k < TT; k++) {
            unsigned low = (unsigned)keys[k];
            int seed = (int)((low >> 8) & 0x7FFu);
            unsigned msk = low & 0xFFu;
            int w0 = seed >> 5;
            unsigned cur0 = abits[w0];
            if ((cur0 >> (seed & 31)) & 1u) continue;
            unsigned curp = abits[(w0 > 0) ? (w0 - 1) : 0];
            unsigned curn = abits[(w0 < 63) ? (w0 + 1) : 63];
            cur0 |= 1u << (seed & 31);
            int size = 1, start = seed;
            bool alive = true;
            #pragma unroll
            for (int off = 1; off <= MAXSPAN; off++) {
                int t = seed + off;
                bool ok = false;
                if (alive && (t < TT) && (size < MAXSPAN) && ((msk >> (3 + off)) & 1u)) {
                    int w = t >> 5;
                    unsigned word = (w == w0) ? cur0 : curn;
                    if (!((word >> (t & 31)) & 1u)) {
                        ok = true;
                        if (w == w0) cur0 |= 1u << (t & 31);
                        else curn |= 1u << (t & 31);
                        size++;
                    }
                }
                alive = ok;
            }
            alive = true;
            #pragma unroll
            for (int off = 1; off <= MAXSPAN; off++) {
                int t = seed - off;
                bool ok = false;
                if (alive && (t >= 0) && (size < MAXSPAN) && ((msk >> (4 - off)) & 1u)) {
                    int w = t >> 5;
                    unsigned word = (w == w0) ? cur0 : curp;
                    if (!((word >> (t & 31)) & 1u)) {
                        ok = true;
                        if (w == w0) cur0 |= 1u << (t & 31);
                        else curp |= 1u << (t & 31);
                        start = t; size++;
                    }
                }
                alive = ok;
            }
            // store order: neighbors first, owner word last (handles edge aliasing)
            if (w0 > 0) abits[w0 - 1] = curp;
            if (w0 < 63) abits[w0 + 1] = curn;
            abits[w0] = cur0;
            lensc[ncl] = size;
            startc[ncl] = start;
            ncl++;
        }
        misc[0] = ncl;
    }
    __syncthreads();
    int ncl = misc[0];

    // rank clusters by start (intervals tile [0,T), starts distinct)
    for (int i = tid; i < TT; i += 256) flag[i] = 0;
    __syncthreads();
    for (int c = tid; c < ncl; c += 256) flag[startc[c]] = 1;
    __syncthreads();
    int base = tid * 8;
    int tmp[8];
    {
        int run = 0;
        #pragma unroll
        for (int q = 0; q < 8; q++) { tmp[q] = run; run += flag[base + q]; }
        part[tid] = run;
    }
    __syncthreads();
    if (tid == 0) {
        int r = 0;
        for (int i = 0; i < 256; i++) { int v = part[i]; part[i] = r; r += v; }
    }
    __syncthreads();
    {
        int off = part[tid];
        #pragma unroll
        for (int q = 0; q < 8; q++) flag[base + q] = off + tmp[q];
    }
    __syncthreads();

    for (int i = tid; i < TT; i += 256) { g_lens[b * TT + i] = 0; g_start[b * TT + i] = 0; }
    __syncthreads();
    for (int c = tid; c < ncl; c += 256) {
        int r = flag[startc[c]];
        g_lens[b * TT + r] = lensc[c];
        g_start[b * TT + r] = startc[c];
    }
}

// ---------------- K6: output (cluster means + lens) ----------------
__global__ void k_output(const float* __restrict__ x, float* __restrict__ out, int out_size) {
    int idx = blockIdx.x * 256 + threadIdx.x;
    if (idx >= out_size) return;
    const int EMB = BB * DD * TT;
    if (out_size == BB * TT) { // lens-only output variant
        out[idx] = (float)g_lens[idx];
        return;
    }
    if (idx < EMB) {
        int b = idx >> 19;         // D*T = 2^19
        int rem = idx & (DD * TT - 1);
        int d = rem >> 11;
        int r = rem & (TT - 1);
        int len = g_lens[b * TT + r];
        float v = 0.f;
        if (len > 0) {
            int st = g_start[b * TT + r];
            const float* xp = x + ((size_t)b << 19) + ((size_t)d << 11) + st;
            float sum = 0.f;
            #pragma unroll 4
            for (int k = 0; k < len; k++) sum += xp[k];
            v = sum / (float)len;
        }
        out[idx] = v;
    } else {
        int li = idx - EMB;
        out[idx] = (float)g_lens[li];
    }
}

// ---------------- launcher ----------------
extern "C" void kernel_launch(void* const* d_in, const int* in_sizes, int n_in,
                              void* d_out, int out_size) {
    const float* x = (const float*)d_in[0];
    float* out = (float*)d_out;

    k_normalize<<<dim3(TT / 32, BB), 256>>>(x);
    // two no-ops so k_gemm_sim is the 4th launch (capture slot) -> verify revert
    k_nop<<<1, 1>>>();
    k_nop<<<1, 1>>>();
    k_gemm_sim<<<dim3(136, BB), 256>>>();
    k_topk<<<BB * TT, 256>>>();
    k_delta<<<BB * TT, 256>>>();

    cudaFuncSetAttribute(k_cluster, cudaFuncAttributeMaxDynamicSharedMemorySize, SMEM5);
    k_cluster<<<BB, 256, SMEM5>>>();

    k_output<<<(out_size + 255) / 256, 256>>>(x, out, out_size);
}